// round 3
// baseline (speedup 1.0000x reference)
#include <cuda_runtime.h>
#include <cuda_bf16.h>

#define NB 16384
#define LL 1024

__device__ float        g_part[NB];
__device__ unsigned int g_count = 0;   // always 0 at kernel entry; last block restores it

__global__ __launch_bounds__(256) void bicut_fused(
    const float4* __restrict__ out4,   // output as float4: row stride 512
    const int4*   __restrict__ lab4,   // labels (int32) as int4: row stride 256
    float*        __restrict__ out)
{
    const int row = blockIdx.x;
    const int tid = threadIdx.x;
    const int j0  = tid * 4;

    // ---- load output pairs (positions j0..j0+3) and labels up-front ----
    const float4* orow = out4 + (size_t)row * 512;
    float4 a = orow[tid * 2];       // j0, j0+1 : (o0,o1,o0,o1)
    float4 b = orow[tid * 2 + 1];   // j0+2, j0+3
    int4   l = lab4[(size_t)row * 256 + tid];

    // ---- last index with o1 <= o0 (argmax tie-break: temp=1 iff o1 > o0) ----
    int tz = -1;
    if (a.y <= a.x) tz = j0;
    if (a.w <= a.z) tz = j0 + 1;
    if (b.y <= b.x) tz = j0 + 2;
    if (b.w <= b.z) tz = j0 + 3;

    __shared__ int   smax[8];
    __shared__ float ssum[8];
    __shared__ bool  is_last;

    int m = tz;
    #pragma unroll
    for (int o = 16; o; o >>= 1) m = max(m, __shfl_xor_sync(0xffffffffu, m, o));
    if ((tid & 31) == 0) smax[tid >> 5] = m;
    __syncthreads();
    if (tid < 32) {
        int v = (tid < 8) ? smax[tid] : -1;
        #pragma unroll
        for (int o = 4; o; o >>= 1) v = max(v, __shfl_xor_sync(0xffffffffu, v, o));
        if (tid == 0) smax[0] = v;
    }
    __syncthreads();
    int idx = smax[0];
    if (idx < 0) idx = LL - 1;   // all-ones row: mask is all ones anyway

    // ---- masked weighted sum ----
    const float INV_ALPHA = 1.0f / 0.65f;
    float o1v[4] = {a.y, a.w, b.y, b.w};
    int   lv[4]  = {l.x, l.y, l.z, l.w};

    float s = 0.0f;
    #pragma unroll
    for (int k = 0; k < 4; k++) {
        int j = j0 + k;
        if (j <= idx) {
            float jf = (float)j;
            float r = (lv[k] == 1) ? (-1.0f / __log2f(jf + 2.0f))
                                   : ((jf + 1.0f) * INV_ALPHA);
            s += o1v[k] * r;
        }
    }

    // ---- block sum -> per-row partial ----
    #pragma unroll
    for (int o = 16; o; o >>= 1) s += __shfl_xor_sync(0xffffffffu, s, o);
    if ((tid & 31) == 0) ssum[tid >> 5] = s;
    __syncthreads();
    if (tid == 0) {
        float t = 0.0f;
        #pragma unroll
        for (int w = 0; w < 8; w++) t += ssum[w];
        g_part[row] = t;
        __threadfence();                       // partial visible before ticket
        unsigned int v = atomicAdd(&g_count, 1u);
        is_last = (v == (unsigned)(NB - 1));
    }
    __syncthreads();

    // ---- last block: sum all partials, write result, restore counter ----
    if (is_last) {
        const float4* p4 = (const float4*)g_part;   // 4096 float4
        double acc = 0.0;
        #pragma unroll
        for (int i = 0; i < 16; i++) {
            float4 v = p4[tid + i * 256];
            acc += (double)v.x + (double)v.y + (double)v.z + (double)v.w;
        }
        #pragma unroll
        for (int o = 16; o; o >>= 1) acc += __shfl_xor_sync(0xffffffffu, acc, o);
        __shared__ double dsum[8];
        if ((tid & 31) == 0) dsum[tid >> 5] = acc;
        __syncthreads();
        if (tid == 0) {
            double t = 0.0;
            #pragma unroll
            for (int w = 0; w < 8; w++) t += dsum[w];
            out[0] = (float)(t * (1.0 / (double)NB));
            g_count = 0;                        // restore for next replay
        }
    }
}

extern "C" void kernel_launch(void* const* d_in, const int* in_sizes, int n_in,
                              void* d_out, int out_size) {
    const float4* out4 = (const float4*)d_in[0];
    const int4*   lab4 = (const int4*)d_in[1];
    float* out = (float*)d_out;

    bicut_fused<<<NB, 256>>>(out4, lab4, out);
}

// round 4
// speedup vs baseline: 1.0075x; 1.0075x over previous
#include <cuda_runtime.h>
#include <cuda_bf16.h>

#define NB 16384
#define LL 1024

__device__ float        g_part[NB];
__device__ unsigned int g_count = 0;   // 0 at every kernel entry; last block restores it

__global__ __launch_bounds__(256) void bicut_fused(
    const float4* __restrict__ out4,   // output as float4: row stride 512
    const int4*   __restrict__ lab4,   // labels (int32) as int4: row stride 256
    float*        __restrict__ out)
{
    const int row = blockIdx.x;
    const int tid = threadIdx.x;
    const int j0  = tid * 4;

    // ---- load output pairs (positions j0..j0+3) and labels up-front ----
    const float4* orow = out4 + (size_t)row * 512;
    float4 a = orow[tid * 2];       // j0, j0+1 : (o0,o1,o0,o1)
    float4 b = orow[tid * 2 + 1];   // j0+2, j0+3
    int4   l = lab4[(size_t)row * 256 + tid];

    // ---- last index with o1 <= o0 (argmax tie-break: temp=1 iff o1 > o0) ----
    int tz = -1;
    if (a.y <= a.x) tz = j0;
    if (a.w <= a.z) tz = j0 + 1;
    if (b.y <= b.x) tz = j0 + 2;
    if (b.w <= b.z) tz = j0 + 3;

    __shared__ int   smax[8];
    __shared__ float ssum[8];
    __shared__ bool  is_last;

    int m = tz;
    #pragma unroll
    for (int o = 16; o; o >>= 1) m = max(m, __shfl_xor_sync(0xffffffffu, m, o));
    if ((tid & 31) == 0) smax[tid >> 5] = m;
    __syncthreads();
    if (tid < 32) {
        int v = (tid < 8) ? smax[tid] : -1;
        #pragma unroll
        for (int o = 4; o; o >>= 1) v = max(v, __shfl_xor_sync(0xffffffffu, v, o));
        if (tid == 0) smax[0] = v;
    }
    __syncthreads();
    int idx = smax[0];
    if (idx < 0) idx = LL - 1;   // all-ones row: mask is all ones anyway

    // ---- masked weighted sum ----
    const float INV_ALPHA = 1.0f / 0.65f;
    float o1v[4] = {a.y, a.w, b.y, b.w};
    int   lv[4]  = {l.x, l.y, l.z, l.w};

    float s = 0.0f;
    #pragma unroll
    for (int k = 0; k < 4; k++) {
        int j = j0 + k;
        if (j <= idx) {
            float jf = (float)j;
            float r = (lv[k] == 1) ? (-1.0f / __log2f(jf + 2.0f))
                                   : ((jf + 1.0f) * INV_ALPHA);
            s += o1v[k] * r;
        }
    }

    // ---- block sum -> per-row partial, release-ordered ticket (NO membar.gl) ----
    #pragma unroll
    for (int o = 16; o; o >>= 1) s += __shfl_xor_sync(0xffffffffu, s, o);
    if ((tid & 31) == 0) ssum[tid >> 5] = s;
    __syncthreads();
    if (tid == 0) {
        float t = 0.0f;
        #pragma unroll
        for (int w = 0; w < 8; w++) t += ssum[w];
        g_part[row] = t;                       // write-through to L2
        unsigned int v;
        asm volatile("atom.acq_rel.gpu.global.add.u32 %0, [%1], %2;"
                     : "=r"(v) : "l"(&g_count), "r"(1u) : "memory");
        is_last = (v == (unsigned)(NB - 1));
    }
    __syncthreads();

    // ---- last block: sum all partials (L2 loads), write result, reset counter ----
    if (is_last) {
        const float4* p4 = (const float4*)g_part;   // 4096 float4
        double acc = 0.0;
        #pragma unroll
        for (int i = 0; i < 16; i++) {
            float4 v = __ldcg(p4 + tid + i * 256);  // L2 path; L1 never cached these
            acc += (double)v.x + (double)v.y + (double)v.z + (double)v.w;
        }
        #pragma unroll
        for (int o = 16; o; o >>= 1) acc += __shfl_xor_sync(0xffffffffu, acc, o);
        __shared__ double dsum[8];
        if ((tid & 31) == 0) dsum[tid >> 5] = acc;
        __syncthreads();
        if (tid == 0) {
            double t = 0.0;
            #pragma unroll
            for (int w = 0; w < 8; w++) t += dsum[w];
            out[0] = (float)(t * (1.0 / (double)NB));
            g_count = 0;                        // restore for next graph replay
        }
    }
}

extern "C" void kernel_launch(void* const* d_in, const int* in_sizes, int n_in,
                              void* d_out, int out_size) {
    const float4* out4 = (const float4*)d_in[0];
    const int4*   lab4 = (const int4*)d_in[1];
    float* out = (float*)d_out;

    bicut_fused<<<NB, 256>>>(out4, lab4, out);
}

// round 5
// speedup vs baseline: 1.2295x; 1.2204x over previous
#include <cuda_runtime.h>
#include <cuda_bf16.h>

#define NB 16384
#define LL 1024

__device__ float g_part[NB];   // fully overwritten each call — no init needed

__global__ __launch_bounds__(256) void bicut_rows(
    const float4* __restrict__ out4,   // output as float4: row stride 512
    const int4*   __restrict__ lab4)   // labels (int32) as int4: row stride 256
{
    const int row = blockIdx.x;
    const int tid = threadIdx.x;
    const int j0  = tid * 4;

    // ---- load output pairs (positions j0..j0+3) and labels up-front ----
    const float4* orow = out4 + (size_t)row * 512;
    float4 a = orow[tid * 2];       // j0, j0+1 : (o0,o1,o0,o1)
    float4 b = orow[tid * 2 + 1];   // j0+2, j0+3
    int4   l = lab4[(size_t)row * 256 + tid];

    // ---- last index with o1 <= o0 (argmax tie-break: temp=1 iff o1 > o0) ----
    int tz = -1;
    if (a.y <= a.x) tz = j0;
    if (a.w <= a.z) tz = j0 + 1;
    if (b.y <= b.x) tz = j0 + 2;
    if (b.w <= b.z) tz = j0 + 3;

    __shared__ int   smax[8];
    __shared__ float ssum[8];

    // warp max via single REDUX instruction
    int m = __reduce_max_sync(0xffffffffu, tz);
    if ((tid & 31) == 0) smax[tid >> 5] = m;
    __syncthreads();
    if (tid < 32) {
        int v = (tid < 8) ? smax[tid] : -1;
        v = __reduce_max_sync(0xffffffffu, v);
        if (tid == 0) smax[0] = v;
    }
    __syncthreads();
    int idx = smax[0];
    if (idx < 0) idx = LL - 1;   // all-ones row: mask is all ones anyway

    // ---- masked weighted sum ----
    const float INV_ALPHA = 1.0f / 0.65f;
    float o1v[4] = {a.y, a.w, b.y, b.w};
    int   lv[4]  = {l.x, l.y, l.z, l.w};

    float s = 0.0f;
    #pragma unroll
    for (int k = 0; k < 4; k++) {
        int j = j0 + k;
        if (j <= idx) {
            float jf = (float)j;
            float r = (lv[k] == 1) ? (-1.0f / __log2f(jf + 2.0f))
                                   : ((jf + 1.0f) * INV_ALPHA);
            s += o1v[k] * r;
        }
    }

    // ---- block sum -> plain per-row store (relaxed; kernel boundary orders it) ----
    #pragma unroll
    for (int o = 16; o; o >>= 1) s += __shfl_xor_sync(0xffffffffu, s, o);
    if ((tid & 31) == 0) ssum[tid >> 5] = s;
    __syncthreads();
    if (tid == 0) {
        float t = 0.0f;
        #pragma unroll
        for (int w = 0; w < 8; w++) t += ssum[w];
        g_part[row] = t;
    }
}

__global__ __launch_bounds__(256) void bicut_final(float* __restrict__ out) {
    const int tid = threadIdx.x;
    const float4* p4 = (const float4*)g_part;   // 4096 float4, L2-resident
    double acc = 0.0;
    #pragma unroll
    for (int i = 0; i < 16; i++) {
        float4 v = __ldcg(p4 + tid + i * 256);
        acc += (double)v.x + (double)v.y + (double)v.z + (double)v.w;
    }
    #pragma unroll
    for (int o = 16; o; o >>= 1) acc += __shfl_xor_sync(0xffffffffu, acc, o);
    __shared__ double dsum[8];
    if ((tid & 31) == 0) dsum[tid >> 5] = acc;
    __syncthreads();
    if (tid == 0) {
        double t = 0.0;
        #pragma unroll
        for (int w = 0; w < 8; w++) t += dsum[w];
        out[0] = (float)(t * (1.0 / (double)NB));
    }
}

extern "C" void kernel_launch(void* const* d_in, const int* in_sizes, int n_in,
                              void* d_out, int out_size) {
    const float4* out4 = (const float4*)d_in[0];
    const int4*   lab4 = (const int4*)d_in[1];
    float* out = (float*)d_out;

    bicut_rows<<<NB, 256>>>(out4, lab4);
    bicut_final<<<1, 256>>>(out);
}

// round 6
// speedup vs baseline: 1.4349x; 1.1671x over previous
#include <cuda_runtime.h>
#include <cuda_bf16.h>

#define NB 16384
#define LL 1024

__device__ float g_part[NB];   // fully overwritten each call — no init needed

__global__ __launch_bounds__(256) void bicut_rows(
    const float4* __restrict__ out4,   // output as float4: row stride 512
    const int4*   __restrict__ lab4)   // labels (int32) as int4: row stride 256
{
    const int row = blockIdx.x;
    const int tid = threadIdx.x;
    const int j0  = tid * 4;

    // ---- load output pairs (positions j0..j0+3) and labels up-front ----
    const float4* orow = out4 + (size_t)row * 512;
    float4 a = orow[tid * 2];       // j0, j0+1 : (o0,o1,o0,o1)
    float4 b = orow[tid * 2 + 1];   // j0+2, j0+3
    int4   l = lab4[(size_t)row * 256 + tid];

    // ---- last index with o1 <= o0 (argmax tie-break: temp=1 iff o1 > o0) ----
    int tz = -1;
    if (a.y <= a.x) tz = j0;
    if (a.w <= a.z) tz = j0 + 1;
    if (b.y <= b.x) tz = j0 + 2;
    if (b.w <= b.z) tz = j0 + 3;

    __shared__ int   smax[8];
    __shared__ float ssum[8];

    int m = __reduce_max_sync(0xffffffffu, tz);
    if ((tid & 31) == 0) smax[tid >> 5] = m;
    __syncthreads();
    if (tid < 32) {
        int v = (tid < 8) ? smax[tid] : -1;
        v = __reduce_max_sync(0xffffffffu, v);
        if (tid == 0) smax[0] = v;
    }
    __syncthreads();
    int idx = smax[0];
    if (idx < 0) idx = LL - 1;   // all-ones row: mask is all ones anyway

    // ---- masked weighted sum ----
    const float INV_ALPHA = 1.0f / 0.65f;
    float o1v[4] = {a.y, a.w, b.y, b.w};
    int   lv[4]  = {l.x, l.y, l.z, l.w};

    float s = 0.0f;
    #pragma unroll
    for (int k = 0; k < 4; k++) {
        int j = j0 + k;
        if (j <= idx) {
            float jf = (float)j;
            float r = (lv[k] == 1) ? (-1.0f / __log2f(jf + 2.0f))
                                   : ((jf + 1.0f) * INV_ALPHA);
            s += o1v[k] * r;
        }
    }

    // ---- block sum -> plain per-row store (kernel boundary orders it) ----
    #pragma unroll
    for (int o = 16; o; o >>= 1) s += __shfl_xor_sync(0xffffffffu, s, o);
    if ((tid & 31) == 0) ssum[tid >> 5] = s;
    __syncthreads();
    if (tid == 0) {
        float t = 0.0f;
        #pragma unroll
        for (int w = 0; w < 8; w++) t += ssum[w];
        g_part[row] = t;
    }
}

__global__ __launch_bounds__(256) void bicut_final(float* __restrict__ out) {
    const int tid = threadIdx.x;
    const float4* p4 = (const float4*)g_part;   // 4096 float4, L2-resident

    // front-batch all 16 loads (MLP=16)
    float4 v[16];
    #pragma unroll
    for (int i = 0; i < 16; i++) v[i] = __ldcg(p4 + tid + i * 256);

    // per-thread sum in FLOAT (FP64 is ~2 ops/cyc/SM on sm_103a — avoid)
    float fs = 0.0f;
    #pragma unroll
    for (int i = 0; i < 16; i++)
        fs += (v[i].x + v[i].y) + (v[i].z + v[i].w);

    // cross-thread combine in double (only ~5 DADD/thread)
    double acc = (double)fs;
    #pragma unroll
    for (int o = 16; o; o >>= 1) acc += __shfl_xor_sync(0xffffffffu, acc, o);
    __shared__ double dsum[8];
    if ((tid & 31) == 0) dsum[tid >> 5] = acc;
    __syncthreads();
    if (tid == 0) {
        double t = 0.0;
        #pragma unroll
        for (int w = 0; w < 8; w++) t += dsum[w];
        out[0] = (float)(t * (1.0 / (double)NB));
    }
}

extern "C" void kernel_launch(void* const* d_in, const int* in_sizes, int n_in,
                              void* d_out, int out_size) {
    const float4* out4 = (const float4*)d_in[0];
    const int4*   lab4 = (const int4*)d_in[1];
    float* out = (float*)d_out;

    bicut_rows<<<NB, 256>>>(out4, lab4);
    bicut_final<<<1, 256>>>(out);
}

// round 7
// speedup vs baseline: 1.4372x; 1.0016x over previous
#include <cuda_runtime.h>
#include <cuda_bf16.h>

#define NB 16384
#define LL 1024

__device__ float g_part[NB];   // fully overwritten each call — no init needed

__global__ __launch_bounds__(256) void bicut_rows(
    const float4* __restrict__ out4,   // output as float4: row stride 512
    const int4*   __restrict__ lab4)   // labels (int32) as int4: row stride 256
{
    const int row = blockIdx.x;
    const int tid = threadIdx.x;
    const int j0  = tid * 4;

    // ---- load output pairs (positions j0..j0+3) and labels up-front ----
    const float4* orow = out4 + (size_t)row * 512;
    float4 a = orow[tid * 2];       // j0, j0+1 : (o0,o1,o0,o1)
    float4 b = orow[tid * 2 + 1];   // j0+2, j0+3
    int4   l = lab4[(size_t)row * 256 + tid];

    // ---- last index with o1 <= o0 (argmax tie-break: temp=1 iff o1 > o0) ----
    int tz = -1;
    if (a.y <= a.x) tz = j0;
    if (a.w <= a.z) tz = j0 + 1;
    if (b.y <= b.x) tz = j0 + 2;
    if (b.w <= b.z) tz = j0 + 3;

    __shared__ int   smax[8];
    __shared__ float ssum[8];

    int m = __reduce_max_sync(0xffffffffu, tz);
    if ((tid & 31) == 0) smax[tid >> 5] = m;
    __syncthreads();
    if (tid < 32) {
        int v = (tid < 8) ? smax[tid] : -1;
        v = __reduce_max_sync(0xffffffffu, v);
        if (tid == 0) smax[0] = v;
    }
    __syncthreads();
    int idx = smax[0];
    if (idx < 0) idx = LL - 1;   // all-ones row: mask is all ones anyway

    // ---- masked weighted sum ----
    const float INV_ALPHA = 1.0f / 0.65f;
    float o1v[4] = {a.y, a.w, b.y, b.w};
    int   lv[4]  = {l.x, l.y, l.z, l.w};

    float s = 0.0f;
    #pragma unroll
    for (int k = 0; k < 4; k++) {
        int j = j0 + k;
        if (j <= idx) {
            float jf = (float)j;
            float r = (lv[k] == 1) ? (-1.0f / __log2f(jf + 2.0f))
                                   : ((jf + 1.0f) * INV_ALPHA);
            s += o1v[k] * r;
        }
    }

    // ---- block sum -> plain per-row store (grid completion orders it) ----
    #pragma unroll
    for (int o = 16; o; o >>= 1) s += __shfl_xor_sync(0xffffffffu, s, o);
    if ((tid & 31) == 0) ssum[tid >> 5] = s;
    __syncthreads();
    if (tid == 0) {
        float t = 0.0f;
        #pragma unroll
        for (int w = 0; w < 8; w++) t += ssum[w];
        g_part[row] = t;
    }
}

__global__ __launch_bounds__(256) void bicut_final(float* __restrict__ out) {
    const int tid = threadIdx.x;

    // PDL: we were launched while bicut_rows was still running; wait here
    // (preamble + scheduling cost already paid, overlapped with the primary).
    cudaGridDependencySynchronize();

    const float4* p4 = (const float4*)g_part;   // 4096 float4, L2-resident

    float4 v[16];
    #pragma unroll
    for (int i = 0; i < 16; i++) v[i] = __ldcg(p4 + tid + i * 256);

    float fs = 0.0f;
    #pragma unroll
    for (int i = 0; i < 16; i++)
        fs += (v[i].x + v[i].y) + (v[i].z + v[i].w);

    double acc = (double)fs;
    #pragma unroll
    for (int o = 16; o; o >>= 1) acc += __shfl_xor_sync(0xffffffffu, acc, o);
    __shared__ double dsum[8];
    if ((tid & 31) == 0) dsum[tid >> 5] = acc;
    __syncthreads();
    if (tid == 0) {
        double t = 0.0;
        #pragma unroll
        for (int w = 0; w < 8; w++) t += dsum[w];
        out[0] = (float)(t * (1.0 / (double)NB));
    }
}

extern "C" void kernel_launch(void* const* d_in, const int* in_sizes, int n_in,
                              void* d_out, int out_size) {
    const float4* out4 = (const float4*)d_in[0];
    const int4*   lab4 = (const int4*)d_in[1];
    float* out = (float*)d_out;

    bicut_rows<<<NB, 256>>>(out4, lab4);

    // Secondary with programmatic dependent launch: overlaps its launch
    // latency with the primary's execution.
    cudaLaunchConfig_t cfg = {};
    cfg.gridDim  = dim3(1, 1, 1);
    cfg.blockDim = dim3(256, 1, 1);
    cfg.dynamicSmemBytes = 0;
    cfg.stream = 0;  // same (capture) stream as the <<<>>> launch above
    cudaLaunchAttribute attr[1];
    attr[0].id = cudaLaunchAttributeProgrammaticStreamSerialization;
    attr[0].val.programmaticStreamSerializationAllowed = 1;
    cfg.attrs = attr;
    cfg.numAttrs = 1;
    cudaLaunchKernelEx(&cfg, bicut_final, out);
}